// round 5
// baseline (speedup 1.0000x reference)
#include <cuda_runtime.h>
#include <cuda_bf16.h>
#include <mma.h>

using namespace nvcuda;

// Problem constants
#define BSZ   64
#define PP    512
#define DIN   1024
#define DWM   1024
#define NH    16
#define WIN   128
#define HD    64
#define MROWS (BSZ * PP)   // 32768

// ---------------------------------------------------------------------------
// Scratch (device globals — no allocation allowed)
// ---------------------------------------------------------------------------
__device__ float g_q[(size_t)MROWS * DWM];
__device__ float g_k[(size_t)MROWS * DWM];
__device__ float g_v[(size_t)MROWS * DWM];
__device__ float g_o[(size_t)MROWS * DWM];
__device__ int   g_start[BSZ * PP];

// ---------------------------------------------------------------------------
// Prep: detect reset-mask dtype (bool / int32 / float32) and compute, per
// (b, t), the first attended token index:
//   start(b,t) = max(last_reset_index(b, <=t), t - (WIN-1), 0)
// Reading exactly 32768 bytes in the probe is safe for all three dtypes.
// ---------------------------------------------------------------------------
__global__ void prep_kernel(const unsigned char* __restrict__ reset_raw)
{
    __shared__ int s_ni, s_nf, s_any;
    if (threadIdx.x == 0) { s_ni = 0; s_nf = 0; s_any = 0; }
    __syncthreads();

    const unsigned int* w32 = (const unsigned int*)reset_raw;
    int ni = 0, nf = 0, any = 0;
    for (int i = threadIdx.x; i < 8192; i += blockDim.x) {   // 32768 bytes
        unsigned int v = w32[i];
        if (v != 0u) {
            any = 1;
            if (v != 1u)           ni = 1;   // not int32-like
            if (v != 0x3f800000u)  nf = 1;   // not float32-like
        }
    }
    if (ni)  atomicOr(&s_ni, 1);
    if (nf)  atomicOr(&s_nf, 1);
    if (any) atomicOr(&s_any, 1);
    __syncthreads();

    // mode: 0 = bool(1B), 1 = int32, 2 = float32, -1 = no resets observed
    int mode;
    if (!s_any)      mode = -1;
    else if (!s_ni)  mode = 1;
    else if (!s_nf)  mode = 2;
    else             mode = 0;

    for (int b = threadIdx.x; b < BSZ; b += blockDim.x) {
        int r = 0;
        for (int t = 0; t < PP; t++) {
            int idx = b * PP + t;
            bool reset = false;
            if (mode == 0)      reset = (reset_raw[idx] != 0);
            else if (mode > 0)  reset = (w32[idx] != 0u);
            if (reset) r = t;
            int s = t - (WIN - 1);
            if (s < r) s = r;
            if (s < 0) s = 0;
            g_start[idx] = s;
        }
    }
}

// ---------------------------------------------------------------------------
// TF32 tensor-core GEMM: C[M,N] = A[M,K] @ B[K,N] + bias[N]
// Block tile 128x128x32, 8 warps (4x2), warp tile 32x64 (2x4 wmma frags).
// asel: 0 -> A = Aext, 1 -> A = g_o
// csel: 0/1/2 -> g_q/g_k/g_v, 3 -> Cext
// ---------------------------------------------------------------------------
#define GBM 128
#define GBN 128
#define GBK 32
#define LDA 40     // GBK + 8 pad (floats)
#define LDB 136    // GBN + 8 pad
#define LDC 20

__global__ __launch_bounds__(256, 2)
void gemm_tf32_kernel(const float* __restrict__ Aext,
                      const float* __restrict__ Bw,
                      const float* __restrict__ bias,
                      float* __restrict__ Cext,
                      int asel, int csel)
{
    __shared__ __align__(16) float sA[GBM * LDA];
    __shared__ __align__(16) float sB[GBK * LDB];
    __shared__ __align__(16) float sC[8 * 16 * LDC];

    const float* A = asel ? g_o : Aext;
    float* C;
    if (csel == 0)      C = g_q;
    else if (csel == 1) C = g_k;
    else if (csel == 2) C = g_v;
    else                C = Cext;

    const int K = DIN, N = DWM;
    const int bn = blockIdx.x;    // N-dim fastest -> B stays L2-hot, A stripe reused
    const int bm = blockIdx.y;
    const int tid  = threadIdx.x;
    const int warp = tid >> 5;
    const int lane = tid & 31;
    const int wm = warp & 3;      // 4 warps along M
    const int wn = warp >> 2;     // 2 warps along N

    wmma::fragment<wmma::accumulator, 16, 16, 8, float> acc[2][4];
#pragma unroll
    for (int mi = 0; mi < 2; mi++)
#pragma unroll
        for (int ni = 0; ni < 4; ni++)
            wmma::fill_fragment(acc[mi][ni], 0.0f);

    const float* Ab = A + (size_t)bm * GBM * K;
    const float* Bb = Bw + bn * GBN;

    for (int kt = 0; kt < K; kt += GBK) {
        // Load A tile: 128 rows x 32 cols = 1024 float4, 4 per thread
#pragma unroll
        for (int i = 0; i < 4; i++) {
            int idx = tid + i * 256;
            int r  = idx >> 3;
            int c4 = idx & 7;
            float4 tv = *(const float4*)(Ab + (size_t)r * K + kt + c4 * 4);
            *(float4*)(sA + r * LDA + c4 * 4) = tv;
        }
        // Load B tile: 32 rows x 128 cols
#pragma unroll
        for (int i = 0; i < 4; i++) {
            int idx = tid + i * 256;
            int r  = idx >> 5;
            int c4 = idx & 31;
            float4 tv = *(const float4*)(Bb + (size_t)(kt + r) * N + c4 * 4);
            *(float4*)(sB + r * LDB + c4 * 4) = tv;
        }
        __syncthreads();

#pragma unroll
        for (int kk = 0; kk < GBK; kk += 8) {
            wmma::fragment<wmma::matrix_a, 16, 16, 8, wmma::precision::tf32, wmma::row_major> af[2];
            wmma::fragment<wmma::matrix_b, 16, 16, 8, wmma::precision::tf32, wmma::row_major> bf[4];
#pragma unroll
            for (int mi = 0; mi < 2; mi++) {
                wmma::load_matrix_sync(af[mi], sA + (wm * 32 + mi * 16) * LDA + kk, LDA);
#pragma unroll
                for (int e = 0; e < af[mi].num_elements; e++)
                    af[mi].x[e] = wmma::__float_to_tf32(af[mi].x[e]);
            }
#pragma unroll
            for (int ni = 0; ni < 4; ni++) {
                wmma::load_matrix_sync(bf[ni], sB + kk * LDB + wn * 64 + ni * 16, LDB);
#pragma unroll
                for (int e = 0; e < bf[ni].num_elements; e++)
                    bf[ni].x[e] = wmma::__float_to_tf32(bf[ni].x[e]);
            }
#pragma unroll
            for (int mi = 0; mi < 2; mi++)
#pragma unroll
                for (int ni = 0; ni < 4; ni++)
                    wmma::mma_sync(acc[mi][ni], af[mi], bf[ni], acc[mi][ni]);
        }
        __syncthreads();
    }

    // Epilogue: per-warp 16x16 scratch roundtrip, add bias, vectorized store
    float* myC = sC + warp * 16 * LDC;
    const int r  = lane >> 1;
    const int ch = (lane & 1) * 8;
#pragma unroll
    for (int mi = 0; mi < 2; mi++)
#pragma unroll
        for (int ni = 0; ni < 4; ni++) {
            wmma::store_matrix_sync(myC, acc[mi][ni], LDC, wmma::mem_row_major);
            __syncwarp();
            int gm = bm * GBM + wm * 32 + mi * 16 + r;
            int gn = bn * GBN + wn * 64 + ni * 16 + ch;
            float4 o0, o1;
            o0.x = myC[r * LDC + ch + 0] + bias[gn + 0];
            o0.y = myC[r * LDC + ch + 1] + bias[gn + 1];
            o0.z = myC[r * LDC + ch + 2] + bias[gn + 2];
            o0.w = myC[r * LDC + ch + 3] + bias[gn + 3];
            o1.x = myC[r * LDC + ch + 4] + bias[gn + 4];
            o1.y = myC[r * LDC + ch + 5] + bias[gn + 5];
            o1.z = myC[r * LDC + ch + 6] + bias[gn + 6];
            o1.w = myC[r * LDC + ch + 7] + bias[gn + 7];
            *(float4*)(C + (size_t)gm * N + gn)     = o0;
            *(float4*)(C + (size_t)gm * N + gn + 4) = o1;
            __syncwarp();
        }
}

// ---------------------------------------------------------------------------
// Sliding-window attention with doc resets, online softmax.
// Block = (batch b, tile of TQ=8 consecutive queries). 8 warps: warp w owns
// heads 2w, 2w+1; 16 lanes per head, 4 head-dims per lane.
// ---------------------------------------------------------------------------
#define TQ 8

__global__ __launch_bounds__(256)
void attn_kernel()
{
    const int b    = blockIdx.x;
    const int tb   = blockIdx.y * TQ;
    const int warp = threadIdx.x >> 5;
    const int lane = threadIdx.x & 31;
    const int h    = warp * 2 + (lane >> 4);
    const int sub  = lane & 15;
    const int d0   = h * HD + sub * 4;

    const float* qb = g_q + (size_t)b * PP * DWM;
    const float* kb = g_k + (size_t)b * PP * DWM;
    const float* vb = g_v + (size_t)b * PP * DWM;
    float*       ob = g_o + (size_t)b * PP * DWM;

    const float NEG_INF = __int_as_float(0xff800000);

    float4 q4[TQ], acc[TQ];
    float  m[TQ], l[TQ];
    int    st[TQ];
#pragma unroll
    for (int i = 0; i < TQ; i++) {
        int t = tb + i;
        q4[i]  = *(const float4*)(qb + (size_t)t * DWM + d0);
        st[i]  = g_start[b * PP + t];
        m[i]   = NEG_INF;
        l[i]   = 0.0f;
        acc[i] = make_float4(0.f, 0.f, 0.f, 0.f);
    }

    const int jmin = st[0];            // start index is monotone in t
    const int jmax = tb + TQ - 1;

    for (int j = jmin; j <= jmax; j++) {
        float4 k4 = *(const float4*)(kb + (size_t)j * DWM + d0);
        float4 v4 = *(const float4*)(vb + (size_t)j * DWM + d0);
        float s[TQ];
#pragma unroll
        for (int i = 0; i < TQ; i++)
            s[i] = q4[i].x * k4.x + q4[i].y * k4.y + q4[i].z * k4.z + q4[i].w * k4.w;
        // reduce across the 16 lanes of this head
#pragma unroll
        for (int off = 8; off >= 1; off >>= 1)
#pragma unroll
            for (int i = 0; i < TQ; i++)
                s[i] += __shfl_xor_sync(0xffffffffu, s[i], off, 16);

#pragma unroll
        for (int i = 0; i < TQ; i++) {
            int t = tb + i;
            if (j >= st[i] && j <= t) {        // uniform across the warp
                float sc = s[i] * 0.125f;      // 1/sqrt(64)
                float mn = fmaxf(m[i], sc);
                float co = __expf(m[i] - mn);
                float wt = __expf(sc - mn);
                l[i] = l[i] * co + wt;
                acc[i].x = acc[i].x * co + wt * v4.x;
                acc[i].y = acc[i].y * co + wt * v4.y;
                acc[i].z = acc[i].z * co + wt * v4.z;
                acc[i].w = acc[i].w * co + wt * v4.w;
                m[i] = mn;
            }
        }
    }

#pragma unroll
    for (int i = 0; i < TQ; i++) {
        float inv = 1.0f / l[i];
        float4 o = make_float4(acc[i].x * inv, acc[i].y * inv,
                               acc[i].z * inv, acc[i].w * inv);
        *(float4*)(ob + (size_t)(tb + i) * DWM + d0) = o;
    }
}

// ---------------------------------------------------------------------------
// Launch
// ---------------------------------------------------------------------------
extern "C" void kernel_launch(void* const* d_in, const int* in_sizes, int n_in,
                              void* d_out, int out_size)
{
    const float*         x  = (const float*)d_in[0];
    const unsigned char* rs = (const unsigned char*)d_in[1];
    const float* Wq = (const float*)d_in[2];
    const float* bq = (const float*)d_in[3];
    const float* Wk = (const float*)d_in[4];
    const float* bk = (const float*)d_in[5];
    const float* Wv = (const float*)d_in[6];
    const float* bv = (const float*)d_in[7];
    const float* Wo = (const float*)d_in[8];
    const float* bo = (const float*)d_in[9];
    float* y = (float*)d_out;

    prep_kernel<<<1, 256>>>(rs);

    dim3 gg(DWM / GBN, MROWS / GBM);   // (8, 256)
    gemm_tf32_kernel<<<gg, 256>>>(x, Wq, bq, nullptr, 0, 0);  // q
    gemm_tf32_kernel<<<gg, 256>>>(x, Wk, bk, nullptr, 0, 1);  // k
    gemm_tf32_kernel<<<gg, 256>>>(x, Wv, bv, nullptr, 0, 2);  // v

    attn_kernel<<<dim3(BSZ, PP / TQ), 256>>>();

    gemm_tf32_kernel<<<gg, 256>>>(nullptr, Wo, bo, y, 1, 3);  // y = o @ Wo + b
}

// round 7
// speedup vs baseline: 1.1290x; 1.1290x over previous
#include <cuda_runtime.h>
#include <mma.h>
#include <cstdint>

using namespace nvcuda;

// Problem constants
#define BSZ   64
#define PP    512
#define DWM   1024
#define WIN   128
#define MROWS (BSZ * PP)   // 32768
#define TQ    8

// ---------------------------------------------------------------------------
// Scratch (device globals — no allocation allowed)
// ---------------------------------------------------------------------------
__device__ float g_q [(size_t)MROWS * DWM];
__device__ float g_k [(size_t)MROWS * DWM];
__device__ float g_v [(size_t)MROWS * DWM];
__device__ float g_o [(size_t)MROWS * DWM];   // attention out (tf32-rounded)
__device__ float g_xr[(size_t)MROWS * DWM];   // x rounded to tf32
__device__ float g_w [(size_t)4 * 1024 * 1024]; // 4 weights [K,N], tf32-rounded
__device__ float g_bias[4 * 1024];
__device__ int   g_start[BSZ * PP];

// ---------------------------------------------------------------------------
// Helpers (portable PTX only — compute_103 has no tcgen05)
// ---------------------------------------------------------------------------
__device__ __forceinline__ float ftf32(float x) {
    uint32_t u;
    asm("cvt.rn.tf32.f32 %0, %1;" : "=r"(u) : "f"(x));
    return __uint_as_float(u);
}
__device__ __forceinline__ uint32_t smem_u32(const void* p) {
    uint32_t a;
    asm("{ .reg .u64 t; cvta.to.shared.u64 t, %1; cvt.u32.u64 %0, t; }" : "=r"(a) : "l"(p));
    return a;
}
#define CP16(d, s)  asm volatile("cp.async.cg.shared.global [%0], [%1], 16;" :: "r"(d), "l"(s) : "memory")
#define CP_COMMIT() asm volatile("cp.async.commit_group;" ::: "memory")
#define CP_WAIT1()  asm volatile("cp.async.wait_group 1;" ::: "memory")

// ---------------------------------------------------------------------------
// Prep: reset-mask dtype probe + window start indices + bias copy
// ---------------------------------------------------------------------------
__global__ void prep_kernel(const unsigned char* __restrict__ reset_raw,
                            const float* __restrict__ bq, const float* __restrict__ bk,
                            const float* __restrict__ bv, const float* __restrict__ bo)
{
    __shared__ int s_ni, s_nf, s_any;
    if (threadIdx.x == 0) { s_ni = 0; s_nf = 0; s_any = 0; }
    __syncthreads();
    const unsigned int* w32 = (const unsigned int*)reset_raw;
    int ni = 0, nf = 0, any = 0;
    for (int i = threadIdx.x; i < 8192; i += blockDim.x) {   // 32768 bytes, safe all dtypes
        unsigned int v = w32[i];
        if (v != 0u) {
            any = 1;
            if (v != 1u)          ni = 1;
            if (v != 0x3f800000u) nf = 1;
        }
    }
    if (ni)  atomicOr(&s_ni, 1);
    if (nf)  atomicOr(&s_nf, 1);
    if (any) atomicOr(&s_any, 1);
    __syncthreads();
    int mode;
    if (!s_any)      mode = -1;
    else if (!s_ni)  mode = 1;
    else if (!s_nf)  mode = 2;
    else             mode = 0;

    for (int b = threadIdx.x; b < BSZ; b += blockDim.x) {
        int r = 0;
        for (int t = 0; t < PP; t++) {
            int idx = b * PP + t;
            bool reset = false;
            if (mode == 0)      reset = (reset_raw[idx] != 0);
            else if (mode > 0)  reset = (w32[idx] != 0u);
            if (reset) r = t;
            int s = t - (WIN - 1);
            if (s < r) s = r;
            if (s < 0) s = 0;
            g_start[idx] = s;
        }
    }
    for (int i = threadIdx.x; i < 1024; i += blockDim.x) {
        g_bias[i]        = bq[i];
        g_bias[1024 + i] = bk[i];
        g_bias[2048 + i] = bv[i];
        g_bias[3072 + i] = bo[i];
    }
}

// ---------------------------------------------------------------------------
// Round x to tf32 once (HMMA truncation then a no-op -> RN numerics)
// ---------------------------------------------------------------------------
__global__ void round_x_kernel(const float4* __restrict__ x)
{
    size_t i = (size_t)blockIdx.x * blockDim.x + threadIdx.x;
    float4 v = x[i];
    v.x = ftf32(v.x); v.y = ftf32(v.y); v.z = ftf32(v.z); v.w = ftf32(v.w);
    reinterpret_cast<float4*>(g_xr)[i] = v;
}

// Round the 4 weights to tf32 (layout kept [K,N] — row_major B for wmma)
__global__ void round_w_kernel(const float4* __restrict__ W0, const float4* __restrict__ W1,
                               const float4* __restrict__ W2, const float4* __restrict__ W3)
{
    const float4* W = (blockIdx.y == 0) ? W0 : (blockIdx.y == 1) ? W1
                    : (blockIdx.y == 2) ? W2 : W3;
    size_t i = (size_t)blockIdx.x * blockDim.x + threadIdx.x;   // 0..262143
    float4 v = W[i];
    v.x = ftf32(v.x); v.y = ftf32(v.y); v.z = ftf32(v.z); v.w = ftf32(v.w);
    reinterpret_cast<float4*>(g_w)[(size_t)blockIdx.y * 262144 + i] = v;
}

// ---------------------------------------------------------------------------
// Pipelined TF32 WMMA GEMM: C[32768,1024] = A @ W + bias
// Block tile 128x128, K-tile 32, 2-stage cp.async ring, 8 warps (4Mx2N),
// warp tile 32x64. grid.x = 8*nw (bn fast, weight index = blockIdx.x>>3).
//   asel:  0 -> A = g_xr, 1 -> A = g_o
//   wbase: weight/bias/C base index (0 for fused QKV, 3 for output proj)
// ---------------------------------------------------------------------------
#define GBK   32
#define LDAp  40            // 32 + 8 pad
#define LDBp  136           // 128 + 8 pad
#define STG_A (128 * LDAp)              // 5120 floats
#define STG_F (STG_A + GBK * LDBp)      // 9472 floats
#define STG_B_OFF (STG_A * 4)           // 20480 bytes
#define STG_BYTES (STG_F * 4)           // 37888 bytes
#define GSMEM (2 * STG_BYTES)           // 75776 bytes

__global__ __launch_bounds__(256, 2)
void gemm_tf32_kernel(float* __restrict__ Cext, int asel, int wbase)
{
    extern __shared__ float smem[];
    const uint32_t sb = smem_u32(smem);
    const int tid = threadIdx.x, warp = tid >> 5, lane = tid & 31;
    const int w  = wbase + (blockIdx.x >> 3);
    const int bn = blockIdx.x & 7;
    const int bm = blockIdx.y;
    const int wm = warp & 3;      // 4 warps along M
    const int wn = warp >> 2;     // 2 warps along N

    const float* A  = asel ? g_o : g_xr;
    const float* Bw = g_w + (size_t)w * 1048576 + bn * 128;
    float* C = (w == 0) ? g_q : (w == 1) ? g_k : (w == 2) ? g_v : Cext;
    const float* bias = g_bias + w * 1024;

    const float* Ab = A + (size_t)bm * 128 * 1024;

    // Per-thread cp.async plan: 4 A-chunks + 4 B-chunks of 16B per k-tile
    const float* asrc[4]; const float* bsrc[4];
    uint32_t aoff[4], boff[4];
#pragma unroll
    for (int i = 0; i < 4; i++) {
        int idx = tid + i * 256;
        {   // A tile: 128 rows x 32 cols
            int r = idx >> 3, c4 = idx & 7;
            asrc[i] = Ab + (size_t)r * 1024 + c4 * 4;
            aoff[i] = (uint32_t)(r * LDAp + c4 * 4) * 4;
        }
        {   // B tile: 32 rows (K) x 128 cols (N)
            int r = idx >> 5, c4 = idx & 31;
            bsrc[i] = Bw + (size_t)r * 1024 + c4 * 4;
            boff[i] = STG_B_OFF + (uint32_t)(r * LDBp + c4 * 4) * 4;
        }
    }

    wmma::fragment<wmma::accumulator, 16, 16, 8, float> acc[2][4];
#pragma unroll
    for (int mi = 0; mi < 2; mi++)
#pragma unroll
        for (int ni = 0; ni < 4; ni++)
            wmma::fill_fragment(acc[mi][ni], 0.0f);

    // Prologue: tile 0 -> stage 0
#pragma unroll
    for (int i = 0; i < 4; i++) CP16(sb + aoff[i], asrc[i]);
#pragma unroll
    for (int i = 0; i < 4; i++) CP16(sb + boff[i], bsrc[i]);
    CP_COMMIT();

    for (int t = 0; t < 32; t++) {
        const int s = t & 1;
        if (t + 1 < 32) {   // prefetch next tile into the other stage
            uint32_t st = sb + (s ^ 1) * STG_BYTES;
#pragma unroll
            for (int i = 0; i < 4; i++) CP16(st + aoff[i], asrc[i] + (t + 1) * 32);
#pragma unroll
            for (int i = 0; i < 4; i++) CP16(st + boff[i], bsrc[i] + (size_t)(t + 1) * 32 * 1024);
        }
        CP_COMMIT();
        CP_WAIT1();          // tile t landed (this thread)
        __syncthreads();     // ... for all threads

        const float* sA  = smem + s * STG_F;
        const float* sBt = sA + STG_A;
#pragma unroll
        for (int kk = 0; kk < GBK; kk += 8) {
            wmma::fragment<wmma::matrix_a, 16, 16, 8, wmma::precision::tf32, wmma::row_major> af[2];
            wmma::fragment<wmma::matrix_b, 16, 16, 8, wmma::precision::tf32, wmma::row_major> bf[4];
#pragma unroll
            for (int mi = 0; mi < 2; mi++)
                wmma::load_matrix_sync(af[mi], sA + (wm * 32 + mi * 16) * LDAp + kk, LDAp);
#pragma unroll
            for (int ni = 0; ni < 4; ni++)
                wmma::load_matrix_sync(bf[ni], sBt + kk * LDBp + wn * 64 + ni * 16, LDBp);
            // operands pre-rounded to tf32 -> no per-element cvt needed
#pragma unroll
            for (int mi = 0; mi < 2; mi++)
#pragma unroll
                for (int ni = 0; ni < 4; ni++)
                    wmma::mma_sync(acc[mi][ni], af[mi], bf[ni], acc[mi][ni]);
        }
        __syncthreads();     // stage s free for reuse next-next iteration
    }

    // Epilogue: per-warp 16x16 scratch roundtrip, bias add, float4 stores
    float* myC = smem + warp * 16 * 20;
    const int r  = lane >> 1;
    const int ch = (lane & 1) * 8;
#pragma unroll
    for (int mi = 0; mi < 2; mi++)
#pragma unroll
        for (int ni = 0; ni < 4; ni++) {
            wmma::store_matrix_sync(myC, acc[mi][ni], 20, wmma::mem_row_major);
            __syncwarp();
            int gm = bm * 128 + wm * 32 + mi * 16 + r;
            int gn = bn * 128 + wn * 64 + ni * 16 + ch;
            float4 o0, o1;
            o0.x = myC[r * 20 + ch + 0] + bias[gn + 0];
            o0.y = myC[r * 20 + ch + 1] + bias[gn + 1];
            o0.z = myC[r * 20 + ch + 2] + bias[gn + 2];
            o0.w = myC[r * 20 + ch + 3] + bias[gn + 3];
            o1.x = myC[r * 20 + ch + 4] + bias[gn + 4];
            o1.y = myC[r * 20 + ch + 5] + bias[gn + 5];
            o1.z = myC[r * 20 + ch + 6] + bias[gn + 6];
            o1.w = myC[r * 20 + ch + 7] + bias[gn + 7];
            *(float4*)(C + (size_t)gm * 1024 + gn)     = o0;
            *(float4*)(C + (size_t)gm * 1024 + gn + 4) = o1;
            __syncwarp();
        }
}

// ---------------------------------------------------------------------------
// Sliding-window attention with doc resets, online softmax.
// Block = (batch b, tile of TQ=8 queries). Warp w owns heads 2w,2w+1;
// 16 lanes/head, 4 head-dims/lane. Output tf32-rounded for the final GEMM.
// ---------------------------------------------------------------------------
__global__ __launch_bounds__(256)
void attn_kernel()
{
    const int b    = blockIdx.x;
    const int tb   = blockIdx.y * TQ;
    const int warp = threadIdx.x >> 5;
    const int lane = threadIdx.x & 31;
    const int h    = warp * 2 + (lane >> 4);
    const int sub  = lane & 15;
    const int d0   = h * 64 + sub * 4;

    const float* qb = g_q + (size_t)b * PP * DWM;
    const float* kb = g_k + (size_t)b * PP * DWM;
    const float* vb = g_v + (size_t)b * PP * DWM;
    float*       ob = g_o + (size_t)b * PP * DWM;

    const float NEG_INF = __int_as_float(0xff800000);

    float4 q4[TQ], acc[TQ];
    float  m[TQ], l[TQ];
    int    st[TQ];
#pragma unroll
    for (int i = 0; i < TQ; i++) {
        int t = tb + i;
        q4[i]  = *(const float4*)(qb + (size_t)t * DWM + d0);
        st[i]  = g_start[b * PP + t];
        m[i]   = NEG_INF;
        l[i]   = 0.0f;
        acc[i] = make_float4(0.f, 0.f, 0.f, 0.f);
    }

    const int jmin = st[0];            // start index monotone in t
    const int jmax = tb + TQ - 1;

    for (int j = jmin; j <= jmax; j++) {
        float4 k4 = *(const float4*)(kb + (size_t)j * DWM + d0);
        float4 v4 = *(const float4*)(vb + (size_t)j * DWM + d0);
        float s[TQ];
#pragma unroll
        for (int i = 0; i < TQ; i++)
            s[i] = q4[i].x * k4.x + q4[i].y * k4.y + q4[i].z * k4.z + q4[i].w * k4.w;
#pragma unroll
        for (int off = 8; off >= 1; off >>= 1)
#pragma unroll
            for (int i = 0; i < TQ; i++)
                s[i] += __shfl_xor_sync(0xffffffffu, s[i], off, 16);

#pragma unroll
        for (int i = 0; i < TQ; i++) {
            int t = tb + i;
            if (j >= st[i] && j <= t) {
                float sc = s[i] * 0.125f;
                float mn = fmaxf(m[i], sc);
                float co = __expf(m[i] - mn);
                float wt = __expf(sc - mn);
                l[i] = l[i] * co + wt;
                acc[i].x = acc[i].x * co + wt * v4.x;
                acc[i].y = acc[i].y * co + wt * v4.y;
                acc[i].z = acc[i].z * co + wt * v4.z;
                acc[i].w = acc[i].w * co + wt * v4.w;
                m[i] = mn;
            }
        }
    }

#pragma unroll
    for (int i = 0; i < TQ; i++) {
        float inv = 1.0f / l[i];
        float4 o = make_float4(ftf32(acc[i].x * inv), ftf32(acc[i].y * inv),
                               ftf32(acc[i].z * inv), ftf32(acc[i].w * inv));
        *(float4*)(ob + (size_t)(tb + i) * DWM + d0) = o;
    }
}

// ---------------------------------------------------------------------------
// Launch
// ---------------------------------------------------------------------------
extern "C" void kernel_launch(void* const* d_in, const int* in_sizes, int n_in,
                              void* d_out, int out_size)
{
    const float*         x  = (const float*)d_in[0];
    const unsigned char* rs = (const unsigned char*)d_in[1];
    const float* Wq = (const float*)d_in[2];
    const float* bq = (const float*)d_in[3];
    const float* Wk = (const float*)d_in[4];
    const float* bk = (const float*)d_in[5];
    const float* Wv = (const float*)d_in[6];
    const float* bv = (const float*)d_in[7];
    const float* Wo = (const float*)d_in[8];
    const float* bo = (const float*)d_in[9];
    float* y = (float*)d_out;

    cudaFuncSetAttribute(gemm_tf32_kernel,
                         cudaFuncAttributeMaxDynamicSharedMemorySize, GSMEM);

    prep_kernel<<<1, 256>>>(rs, bq, bk, bv, bo);
    round_x_kernel<<<32768, 256>>>((const float4*)x);
    round_w_kernel<<<dim3(1024, 4), 256>>>((const float4*)Wq, (const float4*)Wk,
                                           (const float4*)Wv, (const float4*)Wo);

    // Fused Q,K,V projections: grid.x = 3 weights * 8 bn (bn fast -> A stripe
    // shared by 24 CTAs, weights L2-resident)
    gemm_tf32_kernel<<<dim3(24, 256), 256, GSMEM>>>(nullptr, 0, 0);

    attn_kernel<<<dim3(BSZ, PP / TQ), 256>>>();

    // y = attn_out @ Wo + bo
    gemm_tf32_kernel<<<dim3(8, 256), 256, GSMEM>>>(y, 1, 3);
}